// round 13
// baseline (speedup 1.0000x reference)
#include <cuda_runtime.h>
#include <cuda_fp16.h>

#define FD    128          // feature dim D
#define NBRS  32           // neighbors per node M
#define ACOEF 0.9f         // residual mixing coefficient
#define ESHIFT 4.0f        // constant logit shift (cancels in normalization)
#define MAXN  50001        // N + 1 pad row
#define PADN  50004        // MAXN rounded up to float4
#define GRID  152          // GB300 SM count
#define THR   1024

typedef unsigned long long u64;

// Per-row precomputed:
//   g_p[i]    = p_i = exp(e_i - ESHIFT),  e_i = x_i @ att[D:]   (row N: 0)
//   g_xh[i,:] = fp16 row  z~[i,d] = x_i[d] * s_i[k(d)]  (capsule sums)
// 256 B/row, 256B-aligned -> exactly 2 cache lines. Row N = zeros.
__device__ float g_p[PADN];
__device__ __align__(256) uint4 g_xh[(size_t)MAXN * 16];

// ---- packed helpers ---------------------------------------------------------
__device__ __forceinline__ void upk2(u64 v, float& lo, float& hi) {
    asm("mov.b64 {%0, %1}, %2;" : "=f"(lo), "=f"(hi) : "l"(v));
}
__device__ __forceinline__ u64 fadd2(u64 a, u64 b) {
    u64 d; asm("add.rn.f32x2 %0, %1, %2;" : "=l"(d) : "l"(a), "l"(b)); return d;
}
// half2 (as u32) -> packed f32x2 in a b64 pair
__device__ __forceinline__ u64 h2f2(unsigned h) {
    u64 r;
    asm("{\n\t.reg .b16 lo, hi;\n\t.reg .f32 flo, fhi;\n\t"
        "mov.b32 {lo, hi}, %1;\n\t"
        "cvt.f32.f16 flo, lo;\n\t"
        "cvt.f32.f16 fhi, hi;\n\t"
        "mov.b64 %0, {flo, fhi};\n\t}"
        : "=l"(r) : "r"(h));
    return r;
}
// fp16x2 fused multiply-add (HFMA2)
__device__ __forceinline__ unsigned hfma2(unsigned a, unsigned b, unsigned c) {
    unsigned d;
    asm("fma.rn.f16x2 %0, %1, %2, %3;" : "=r"(d) : "r"(a), "r"(b), "r"(c));
    return d;
}
// float -> replicated half2
__device__ __forceinline__ unsigned f2h2(float f) {
    unsigned r;
    asm("{\n\t.reg .b16 h;\n\tcvt.rn.f16.f32 h, %1;\n\t"
        "mov.b32 %0, {h, h};\n\t}" : "=r"(r) : "f"(f));
    return r;
}

// ---------------------------------------------------------------------------
// Kernel 1: per-row precompute. One warp per row.
// ---------------------------------------------------------------------------
__global__ __launch_bounds__(256, 8)
void precompute_kernel(const float* __restrict__ x,
                       const float* __restrict__ att,
                       int N)
{
    const int row  = (blockIdx.x * blockDim.x + threadIdx.x) >> 5;
    const int lane = threadIdx.x & 31;
    if (row > N) return;

    float4 v = make_float4(0.f, 0.f, 0.f, 0.f);
    if (row < N) v = __ldg((const float4*)(x + (size_t)row * FD) + lane);
    const float4 a = __ldg((const float4*)(att + FD) + lane);

    // attention logit (full warp reduce) -> p = exp(e - ESHIFT)
    float dot = fmaf(v.x, a.x, fmaf(v.y, a.y, fmaf(v.z, a.z, v.w * a.w)));
#pragma unroll
    for (int off = 16; off; off >>= 1)
        dot += __shfl_xor_sync(0xffffffffu, dot, off);
    if (lane == 0)
        g_p[row] = (row < N) ? __expf(dot - ESHIFT) : 0.f;

    // capsule sum: capsule k = lane>>2 spans 4 lanes (16 elements), fp32 exact
    float cs = (v.x + v.y) + (v.z + v.w);
    cs += __shfl_xor_sync(0xffffffffu, cs, 1);
    cs += __shfl_xor_sync(0xffffffffu, cs, 2);

    // premultiplied fp16 row: z~ = x * s
    __half2 h0 = __float22half2_rn(make_float2(v.x * cs, v.y * cs));
    __half2 h1 = __float22half2_rn(make_float2(v.z * cs, v.w * cs));
    uint2 packed;
    packed.x = *reinterpret_cast<unsigned*>(&h0);
    packed.y = *reinterpret_cast<unsigned*>(&h1);
    ((uint2*)g_xh)[(size_t)row * 32 + lane] = packed;
}

// ---------------------------------------------------------------------------
// Kernel 2: main routing, persistent-style. One block per SM; the whole p
// table lives in SMEM, so the 32 scattered per-node p lookups are LDS
// (4-bank-phase) instead of 32-line LDG replays. HALF-WARP per node,
// R10's gather/consume loop (MLP=4, HFMA2, fp16 flush every 8).
// ---------------------------------------------------------------------------
__global__ __launch_bounds__(THR, 1)
void routing_kernel(const float* __restrict__ x,
                    const int*   __restrict__ nbr,
                    float*       __restrict__ out,
                    int N, int nodesPerBlock, int iters)
{
    extern __shared__ float sp[];          // PADN floats = ~195 KB

    // ---- fill the p table (coalesced float4 copies) -----------------------
    for (int i = threadIdx.x; i < PADN / 4; i += THR)
        ((float4*)sp)[i] = ((const float4*)g_p)[i];
    __syncthreads();

    const int lane = threadIdx.x & 31;
    const int l    = lane & 15;            // lane within half-warp
    const int hw   = threadIdx.x >> 4;     // half-warp id 0..63
    const int base = blockIdx.x * nodesPerBlock;

    for (int it = 0; it < iters; ++it) {
        int n = base + it * 64 + hw;
        if (n >= N) n = N - 1;             // duplicate work, identical values

        // lane l holds neighbors m = 2l and 2l+1
        const int2  ii = __ldg((const int2*)(nbr + (size_t)n * NBRS) + l);
        const float p0 = sp[ii.x];         // LDS: smem-resident p table
        const float p1 = sp[ii.y];

        // normalization over the 32 neighbors (16-lane group)
        float sum = p0 + p1;
#pragma unroll
        for (int off = 8; off; off >>= 1)
            sum += __shfl_xor_sync(0xffffffffu, sum, off, 16);
        const float inv  = ACOEF / sum;
        const float wgt0 = p0 * inv;
        const float wgt1 = p1 * inv;

        u64 acc0 = 0, acc1 = 0, acc2 = 0, acc3 = 0;   // fp32 pairs

#pragma unroll
        for (int ch = 0; ch < NBRS / 8; ++ch) {        // 8-neighbor chunks
            unsigned hac0 = 0, hac1 = 0, hac2 = 0, hac3 = 0;
#pragma unroll
            for (int tb = 0; tb < 2; ++tb) {
                // ---- 4 independent gathers back-to-back (MLP = 4) --------
                uint4 zp[4];
#pragma unroll
                for (int j = 0; j < 4; ++j) {
                    const int t  = ch * 8 + tb * 4 + j;
                    const int im = __shfl_sync(0xffffffffu,
                                       (t & 1) ? ii.y : ii.x, t >> 1, 16);
                    zp[j] = __ldg(&g_xh[(size_t)im * 16 + l]);
                }
                // ---- consume: HFMA2 with broadcast half2 weight -----------
#pragma unroll
                for (int j = 0; j < 4; ++j) {
                    const int      t  = ch * 8 + tb * 4 + j;
                    const float    wf = __shfl_sync(0xffffffffu,
                                           (t & 1) ? wgt1 : wgt0, t >> 1, 16);
                    const unsigned wh = f2h2(wf);
                    hac0 = hfma2(zp[j].x, wh, hac0);
                    hac1 = hfma2(zp[j].y, wh, hac1);
                    hac2 = hfma2(zp[j].z, wh, hac2);
                    hac3 = hfma2(zp[j].w, wh, hac3);
                }
            }
            acc0 = fadd2(acc0, h2f2(hac0));
            acc1 = fadd2(acc1, h2f2(hac1));
            acc2 = fadd2(acc2, h2f2(hac2));
            acc3 = fadd2(acc3, h2f2(hac3));
        }

        // unpack, add residual, store (lane l -> d = 8l..8l+7, coalesced)
        float a0,a1,a2,a3,a4,a5,a6,a7;
        upk2(acc0, a0, a1); upk2(acc1, a2, a3);
        upk2(acc2, a4, a5); upk2(acc3, a6, a7);

        const float4* xr = (const float4*)(x + (size_t)n * FD);
        const float4  x0 = __ldg(xr + 2 * l);
        const float4  x1 = __ldg(xr + 2 * l + 1);
        float4* orow = (float4*)(out + (size_t)n * FD);
        orow[2 * l]     = make_float4(a0 + x0.x, a1 + x0.y,
                                      a2 + x0.z, a3 + x0.w);
        orow[2 * l + 1] = make_float4(a4 + x1.x, a5 + x1.y,
                                      a6 + x1.z, a7 + x1.w);
    }
}

extern "C" void kernel_launch(void* const* d_in, const int* in_sizes, int n_in,
                              void* d_out, int out_size)
{
    const float* x   = (const float*)d_in[0];   // (N, 128)
    const float* att = (const float*)d_in[1];   // (256, 1)
    const int*   nbr = (const int*)d_in[2];     // (N*32,)
    // d_in[3] = max_iter : provably unused (u never depends on routing var p)
    float* out = (float*)d_out;

    const int N = in_sizes[0] / FD;

    const int preBlocks = (N + 1 + 7) / 8;      // rows 0..N (incl. pad record)
    precompute_kernel<<<preBlocks, 256>>>(x, att, N);

    static bool attrSet = false;
    const int smemBytes = PADN * (int)sizeof(float);   // ~195 KB
    if (!attrSet) {
        cudaFuncSetAttribute(routing_kernel,
                             cudaFuncAttributeMaxDynamicSharedMemorySize,
                             smemBytes);
        attrSet = true;
    }

    const int nodesPerBlock = (N + GRID - 1) / GRID;
    const int iters         = (nodesPerBlock + 63) / 64;
    routing_kernel<<<GRID, THR, smemBytes>>>(x, nbr, out, N,
                                             nodesPerBlock, iters);
}

// round 14
// speedup vs baseline: 1.0968x; 1.0968x over previous
#include <cuda_runtime.h>
#include <cuda_fp16.h>

#define FD    128          // feature dim D
#define NBRS  32           // neighbors per node M
#define ACOEF 0.9f         // residual mixing coefficient
#define ESHIFT 4.0f        // constant logit shift (cancels in normalization)
#define MAXN  50001        // N + 1 pad row

typedef unsigned long long u64;

// Per-row precomputed:
//   g_p[i]    = p_i = exp(e_i - ESHIFT),  e_i = x_i @ att[D:]   (row N: 0)
//   g_xh[i,:] = fp16 row  z2[i,d] = p_i * x_i[d] * s_i[k(d)]  (capsule sums)
// Per-node precomputed (sump_kernel):
//   g_inv[n]  = ACOEF / sum_m p_{nbr[n,m]}
// u[n,d] = g_inv[n] * sum_m z2[nbr_m, d] + x[n,d] — main loop is a PURE SUM.
__device__ float g_p[MAXN];
__device__ float g_inv[MAXN - 1];
__device__ __align__(256) uint4 g_xh[(size_t)MAXN * 16];

// ---- packed helpers ---------------------------------------------------------
__device__ __forceinline__ void upk2(u64 v, float& lo, float& hi) {
    asm("mov.b64 {%0, %1}, %2;" : "=f"(lo), "=f"(hi) : "l"(v));
}
__device__ __forceinline__ u64 fadd2(u64 a, u64 b) {
    u64 d; asm("add.rn.f32x2 %0, %1, %2;" : "=l"(d) : "l"(a), "l"(b)); return d;
}
// half2 (as u32) -> packed f32x2 in a b64 pair
__device__ __forceinline__ u64 h2f2(unsigned h) {
    u64 r;
    asm("{\n\t.reg .b16 lo, hi;\n\t.reg .f32 flo, fhi;\n\t"
        "mov.b32 {lo, hi}, %1;\n\t"
        "cvt.f32.f16 flo, lo;\n\t"
        "cvt.f32.f16 fhi, hi;\n\t"
        "mov.b64 %0, {flo, fhi};\n\t}"
        : "=l"(r) : "r"(h));
    return r;
}
// fp16x2 add (HADD2)
__device__ __forceinline__ unsigned hadd2(unsigned a, unsigned b) {
    unsigned d;
    asm("add.rn.f16x2 %0, %1, %2;" : "=r"(d) : "r"(a), "r"(b));
    return d;
}

// ---------------------------------------------------------------------------
// Kernel 1: per-row precompute. One warp per row.
// ---------------------------------------------------------------------------
__global__ __launch_bounds__(256, 8)
void precompute_kernel(const float* __restrict__ x,
                       const float* __restrict__ att,
                       int N)
{
    const int row  = (blockIdx.x * blockDim.x + threadIdx.x) >> 5;
    const int lane = threadIdx.x & 31;
    if (row > N) return;

    float4 v = make_float4(0.f, 0.f, 0.f, 0.f);
    if (row < N) v = __ldg((const float4*)(x + (size_t)row * FD) + lane);
    const float4 a = __ldg((const float4*)(att + FD) + lane);

    // attention logit (full warp reduce -> all lanes)
    float dot = fmaf(v.x, a.x, fmaf(v.y, a.y, fmaf(v.z, a.z, v.w * a.w)));
#pragma unroll
    for (int off = 16; off; off >>= 1)
        dot += __shfl_xor_sync(0xffffffffu, dot, off);

    const float p = (row < N) ? __expf(dot - ESHIFT) : 0.f;
    if (lane == 0) g_p[row] = p;

    // capsule sum: capsule k = lane>>2 spans 4 lanes (16 elements), fp32 exact
    float cs = (v.x + v.y) + (v.z + v.w);
    cs += __shfl_xor_sync(0xffffffffu, cs, 1);
    cs += __shfl_xor_sync(0xffffffffu, cs, 2);

    // fully premultiplied fp16 row: z2 = p * x * s  (single fp16 rounding)
    const float ps = p * cs;
    __half2 h0 = __float22half2_rn(make_float2(v.x * ps, v.y * ps));
    __half2 h1 = __float22half2_rn(make_float2(v.z * ps, v.w * ps));
    uint2 packed;
    packed.x = *reinterpret_cast<unsigned*>(&h0);
    packed.y = *reinterpret_cast<unsigned*>(&h1);
    ((uint2*)g_xh)[(size_t)row * 32 + lane] = packed;
}

// ---------------------------------------------------------------------------
// Kernel 2: per-node normalizer. One warp per node; lane m owns neighbor m.
// The ONLY place that pays the scattered 4-B p gather.
// ---------------------------------------------------------------------------
__global__ __launch_bounds__(256, 8)
void sump_kernel(const int* __restrict__ nbr, int N)
{
    const int n    = (blockIdx.x * blockDim.x + threadIdx.x) >> 5;
    const int lane = threadIdx.x & 31;
    if (n >= N) return;

    const int   idx = __ldg(nbr + (size_t)n * NBRS + lane);
    float sum = __ldg(g_p + idx);
#pragma unroll
    for (int off = 16; off; off >>= 1)
        sum += __shfl_xor_sync(0xffffffffu, sum, off);

    if (lane == 0) g_inv[n] = ACOEF / sum;
}

// ---------------------------------------------------------------------------
// Kernel 3: main routing. HALF-WARP per node (16 lanes x one LDG.128 per
// 256-B row, MLP=4 batches). Inner loop = SHFL(idx) + LDG + 4 HADD2; fp16
// partials flushed to fp32 every 8 neighbors. Prologue is 2 coalesced loads;
// NO scattered scalar loads, NO reduction, NO divide.
// ---------------------------------------------------------------------------
__global__ __launch_bounds__(256, 6)
void routing_kernel(const float* __restrict__ x,
                    const int*   __restrict__ nbr,
                    float*       __restrict__ out,
                    int N)
{
    const int lane = threadIdx.x & 31;
    const int l    = lane & 15;            // lane within half-warp
    int n = blockIdx.x * 16 + (threadIdx.x >> 5) * 2 + (lane >> 4);
    if (n >= N) n = N - 1;                 // exact for N % 16 == 0

    // lane l holds neighbors m = 2l and 2l+1 (order irrelevant to the result)
    const int2  ii  = __ldg((const int2*)(nbr + (size_t)n * NBRS) + l);
    const float inv = __ldg(g_inv + n);    // broadcast within half-warp

    u64 acc0 = 0, acc1 = 0, acc2 = 0, acc3 = 0;   // fp32 pairs (final)

#pragma unroll
    for (int ch = 0; ch < NBRS / 8; ++ch) {        // 8-neighbor fp16 chunks
        unsigned hac0 = 0, hac1 = 0, hac2 = 0, hac3 = 0;  // half2 partials
#pragma unroll
        for (int tb = 0; tb < 2; ++tb) {
            // ---- issue 4 independent gathers back-to-back (MLP = 4) ------
            uint4 zp[4];
#pragma unroll
            for (int j = 0; j < 4; ++j) {
                const int t  = ch * 8 + tb * 4 + j;    // compile-time const
                const int im = __shfl_sync(0xffffffffu,
                                           (t & 1) ? ii.y : ii.x, t >> 1, 16);
                zp[j] = __ldg(&g_xh[(size_t)im * 16 + l]);
            }
            // ---- consume: pure fp16 adds ----------------------------------
#pragma unroll
            for (int j = 0; j < 4; ++j) {
                hac0 = hadd2(zp[j].x, hac0);
                hac1 = hadd2(zp[j].y, hac1);
                hac2 = hadd2(zp[j].z, hac2);
                hac3 = hadd2(zp[j].w, hac3);
            }
        }
        // flush fp16 partials into fp32 accumulators
        acc0 = fadd2(acc0, h2f2(hac0));
        acc1 = fadd2(acc1, h2f2(hac1));
        acc2 = fadd2(acc2, h2f2(hac2));
        acc3 = fadd2(acc3, h2f2(hac3));
    }

    // epilogue: u = inv * q + x
    float a0,a1,a2,a3,a4,a5,a6,a7;
    upk2(acc0, a0, a1); upk2(acc1, a2, a3);
    upk2(acc2, a4, a5); upk2(acc3, a6, a7);

    const float4* xr = (const float4*)(x + (size_t)n * FD);
    const float4  x0 = __ldg(xr + 2 * l);
    const float4  x1 = __ldg(xr + 2 * l + 1);
    float4* orow = (float4*)(out + (size_t)n * FD);
    orow[2 * l]     = make_float4(fmaf(a0, inv, x0.x), fmaf(a1, inv, x0.y),
                                  fmaf(a2, inv, x0.z), fmaf(a3, inv, x0.w));
    orow[2 * l + 1] = make_float4(fmaf(a4, inv, x1.x), fmaf(a5, inv, x1.y),
                                  fmaf(a6, inv, x1.z), fmaf(a7, inv, x1.w));
}

extern "C" void kernel_launch(void* const* d_in, const int* in_sizes, int n_in,
                              void* d_out, int out_size)
{
    const float* x   = (const float*)d_in[0];   // (N, 128)
    const float* att = (const float*)d_in[1];   // (256, 1)
    const int*   nbr = (const int*)d_in[2];     // (N*32,)
    // d_in[3] = max_iter : provably unused (u never depends on routing var p)
    float* out = (float*)d_out;

    const int N = in_sizes[0] / FD;

    const int preBlocks = (N + 1 + 7) / 8;      // rows 0..N (incl. pad record)
    precompute_kernel<<<preBlocks, 256>>>(x, att, N);

    const int sumBlocks = (N + 7) / 8;          // one warp per node
    sump_kernel<<<sumBlocks, 256>>>(nbr, N);

    const int mainBlocks = (N + 15) / 16;       // 16 nodes per 256-thread block
    routing_kernel<<<mainBlocks, 256>>>(x, nbr, out, N);
}

// round 15
// speedup vs baseline: 1.2153x; 1.1080x over previous
#include <cuda_runtime.h>
#include <cuda_fp16.h>

#define FD    128          // feature dim D
#define NBRS  32           // neighbors per node M
#define ACOEF 0.9f         // residual mixing coefficient
#define MAXN  50001        // N + 1 pad row

typedef unsigned long long u64;

// Per-row precomputed: attention logit e_i = x_i @ att[D:], and a PREMULTIPLIED
// fp16 gather table  z~[i,d] = x[i,d] * s_i[k(d)]  (s_i[k] = capsule sum).
// 256 B/row, 256B-aligned -> exactly 2 cache lines. Row N = zeros.
// u[n,d] = A * sum_m w_m * z~[nbr_m, d] + x[n,d].
__device__ float g_e[MAXN];
__device__ __align__(256) uint4 g_xh[(size_t)MAXN * 16];

// ---- packed helpers ---------------------------------------------------------
__device__ __forceinline__ void upk2(u64 v, float& lo, float& hi) {
    asm("mov.b64 {%0, %1}, %2;" : "=f"(lo), "=f"(hi) : "l"(v));
}
__device__ __forceinline__ u64 fadd2(u64 a, u64 b) {
    u64 d; asm("add.rn.f32x2 %0, %1, %2;" : "=l"(d) : "l"(a), "l"(b)); return d;
}
// half2 (as u32) -> packed f32x2 in a b64 pair
__device__ __forceinline__ u64 h2f2(unsigned h) {
    u64 r;
    asm("{\n\t.reg .b16 lo, hi;\n\t.reg .f32 flo, fhi;\n\t"
        "mov.b32 {lo, hi}, %1;\n\t"
        "cvt.f32.f16 flo, lo;\n\t"
        "cvt.f32.f16 fhi, hi;\n\t"
        "mov.b64 %0, {flo, fhi};\n\t}"
        : "=l"(r) : "r"(h));
    return r;
}
// fp16x2 fused multiply-add (HFMA2)
__device__ __forceinline__ unsigned hfma2(unsigned a, unsigned b, unsigned c) {
    unsigned d;
    asm("fma.rn.f16x2 %0, %1, %2, %3;" : "=r"(d) : "r"(a), "r"(b), "r"(c));
    return d;
}
// float -> replicated half2
__device__ __forceinline__ unsigned f2h2(float f) {
    unsigned r;
    asm("{\n\t.reg .b16 h;\n\tcvt.rn.f16.f32 h, %1;\n\t"
        "mov.b32 %0, {h, h};\n\t}" : "=r"(r) : "f"(f));
    return r;
}

// ---------------------------------------------------------------------------
// Kernel 1: per-row precompute. One warp per row.
// ---------------------------------------------------------------------------
__global__ __launch_bounds__(256, 8)
void precompute_kernel(const float* __restrict__ x,
                       const float* __restrict__ att,
                       int N)
{
    const int row  = (blockIdx.x * blockDim.x + threadIdx.x) >> 5;
    const int lane = threadIdx.x & 31;
    if (row > N) return;

    float4 v = make_float4(0.f, 0.f, 0.f, 0.f);
    if (row < N) v = __ldg((const float4*)(x + (size_t)row * FD) + lane);
    const float4 a = __ldg((const float4*)(att + FD) + lane);

    // attention logit (full warp reduce)
    float dot = fmaf(v.x, a.x, fmaf(v.y, a.y, fmaf(v.z, a.z, v.w * a.w)));
#pragma unroll
    for (int off = 16; off; off >>= 1)
        dot += __shfl_xor_sync(0xffffffffu, dot, off);
    if (lane == 0) g_e[row] = dot;

    // capsule sum: capsule k = lane>>2 spans 4 lanes (16 elements), fp32 exact
    float cs = (v.x + v.y) + (v.z + v.w);
    cs += __shfl_xor_sync(0xffffffffu, cs, 1);
    cs += __shfl_xor_sync(0xffffffffu, cs, 2);

    // premultiplied fp16 row: z~ = x * s
    __half2 h0 = __float22half2_rn(make_float2(v.x * cs, v.y * cs));
    __half2 h1 = __float22half2_rn(make_float2(v.z * cs, v.w * cs));
    uint2 packed;
    packed.x = *reinterpret_cast<unsigned*>(&h0);
    packed.y = *reinterpret_cast<unsigned*>(&h1);
    ((uint2*)g_xh)[(size_t)row * 32 + lane] = packed;
}

// ---------------------------------------------------------------------------
// Kernel 2: main routing (R10 structure + prologue overlap).
// HALF-WARP per node; 16 lanes x one LDG.128 per 256-B row; MLP=4 batches;
// HFMA2 accumulate, fp16 flush every 8 neighbors. The FIRST gather batch and
// the residual x loads are issued BEFORE the scattered-e softmax chain, so
// the prologue latency hides under real memory work.
// ---------------------------------------------------------------------------
__global__ __launch_bounds__(256, 6)
void routing_kernel(const float* __restrict__ x,
                    const int*   __restrict__ nbr,
                    float*       __restrict__ out,
                    int N)
{
    const int lane = threadIdx.x & 31;
    const int l    = lane & 15;            // lane within half-warp
    int n = blockIdx.x * 16 + (threadIdx.x >> 5) * 2 + (lane >> 4);
    if (n >= N) n = N - 1;                 // exact for N % 16 == 0

    // lane l holds neighbors m = 2l and 2l+1 (order irrelevant to the result)
    const int2 ii = __ldg((const int2*)(nbr + (size_t)n * NBRS) + l);

    // ---- issue batch 0 gathers + residual x loads BEFORE the softmax ------
    uint4 zp[4];
#pragma unroll
    for (int j = 0; j < 4; ++j) {
        const int im = __shfl_sync(0xffffffffu, (j & 1) ? ii.y : ii.x,
                                   j >> 1, 16);
        zp[j] = __ldg(&g_xh[(size_t)im * 16 + l]);
    }
    const float4* xr = (const float4*)(x + (size_t)n * FD);
    const float4  x0 = __ldg(xr + 2 * l);
    const float4  x1 = __ldg(xr + 2 * l + 1);

    // ---- scattered e loads + softmax (overlapped with the loads above) ----
    const float e0 = __ldg(g_e + ii.x);
    const float e1 = __ldg(g_e + ii.y);
    float mx = fmaxf(e0, e1);
#pragma unroll
    for (int off = 8; off; off >>= 1)
        mx = fmaxf(mx, __shfl_xor_sync(0xffffffffu, mx, off, 16));
    const float p0 = __expf(e0 - mx);
    const float p1 = __expf(e1 - mx);
    float sum = p0 + p1;
#pragma unroll
    for (int off = 8; off; off >>= 1)
        sum += __shfl_xor_sync(0xffffffffu, sum, off, 16);
    const float inv = ACOEF / sum;
    // pre-converted half2 weights (shuffled as u32 in-loop)
    const unsigned wh0 = f2h2(p0 * inv);
    const unsigned wh1 = f2h2(p1 * inv);

    u64 acc0 = 0, acc1 = 0, acc2 = 0, acc3 = 0;   // fp32 pairs (final)

#pragma unroll
    for (int ch = 0; ch < NBRS / 8; ++ch) {        // 8-neighbor fp16 chunks
        unsigned hac0 = 0, hac1 = 0, hac2 = 0, hac3 = 0;  // half2 partials
#pragma unroll
        for (int tb = 0; tb < 2; ++tb) {
            // consume current batch, then issue the next one
            uint4 cur[4];
#pragma unroll
            for (int j = 0; j < 4; ++j) cur[j] = zp[j];

            const int nb = ch * 8 + tb * 4 + 4;    // first t of next batch
            if (nb < NBRS) {
#pragma unroll
                for (int j = 0; j < 4; ++j) {
                    const int t  = nb + j;
                    const int im = __shfl_sync(0xffffffffu,
                                       (t & 1) ? ii.y : ii.x, t >> 1, 16);
                    zp[j] = __ldg(&g_xh[(size_t)im * 16 + l]);
                }
            }
#pragma unroll
            for (int j = 0; j < 4; ++j) {
                const int      t  = ch * 8 + tb * 4 + j;
                const unsigned wh = __shfl_sync(0xffffffffu,
                                        (t & 1) ? wh1 : wh0, t >> 1, 16);
                hac0 = hfma2(cur[j].x, wh, hac0);
                hac1 = hfma2(cur[j].y, wh, hac1);
                hac2 = hfma2(cur[j].z, wh, hac2);
                hac3 = hfma2(cur[j].w, wh, hac3);
            }
        }
        // flush fp16 partials into fp32 accumulators
        acc0 = fadd2(acc0, h2f2(hac0));
        acc1 = fadd2(acc1, h2f2(hac1));
        acc2 = fadd2(acc2, h2f2(hac2));
        acc3 = fadd2(acc3, h2f2(hac3));
    }

    // epilogue: residual + store (lane l -> d = 8l..8l+7, fully coalesced)
    float a0,a1,a2,a3,a4,a5,a6,a7;
    upk2(acc0, a0, a1); upk2(acc1, a2, a3);
    upk2(acc2, a4, a5); upk2(acc3, a6, a7);

    float4* orow = (float4*)(out + (size_t)n * FD);
    orow[2 * l]     = make_float4(a0 + x0.x, a1 + x0.y, a2 + x0.z, a3 + x0.w);
    orow[2 * l + 1] = make_float4(a4 + x1.x, a5 + x1.y, a6 + x1.z, a7 + x1.w);
}

extern "C" void kernel_launch(void* const* d_in, const int* in_sizes, int n_in,
                              void* d_out, int out_size)
{
    const float* x   = (const float*)d_in[0];   // (N, 128)
    const float* att = (const float*)d_in[1];   // (256, 1)
    const int*   nbr = (const int*)d_in[2];     // (N*32,)
    // d_in[3] = max_iter : provably unused (u never depends on routing var p)
    float* out = (float*)d_out;

    const int N = in_sizes[0] / FD;

    const int preBlocks  = (N + 1 + 7) / 8;     // rows 0..N (incl. pad record)
    precompute_kernel<<<preBlocks, 256>>>(x, att, N);

    const int mainBlocks = (N + 15) / 16;       // 16 nodes per 256-thread block
    routing_kernel<<<mainBlocks, 256>>>(x, nbr, out, N);
}

// round 16
// speedup vs baseline: 1.2436x; 1.0233x over previous
#include <cuda_runtime.h>
#include <cuda_fp16.h>

#define FD    128          // feature dim D
#define NBRS  32           // neighbors per node M
#define ACOEF 0.9f         // residual mixing coefficient
#define MAXN  50001        // N + 1 pad row

typedef unsigned long long u64;

// Per-row precomputed: attention logit e_i = x_i @ att[D:], and a PREMULTIPLIED
// fp16 gather table  z~[i,d] = x[i,d] * s_i[k(d)]  (s_i[k] = capsule sum).
// 256 B/row, 256B-aligned -> exactly 2 cache lines. Row N = zeros.
// u[n,d] = A * sum_m w_m * z~[nbr_m, d] + x[n,d].
__device__ float g_e[MAXN];
__device__ __align__(256) uint4 g_xh[(size_t)MAXN * 16];

// ---- packed helpers ---------------------------------------------------------
__device__ __forceinline__ void upk2(u64 v, float& lo, float& hi) {
    asm("mov.b64 {%0, %1}, %2;" : "=f"(lo), "=f"(hi) : "l"(v));
}
__device__ __forceinline__ u64 fadd2(u64 a, u64 b) {
    u64 d; asm("add.rn.f32x2 %0, %1, %2;" : "=l"(d) : "l"(a), "l"(b)); return d;
}
// half2 (as u32) -> packed f32x2 in a b64 pair
__device__ __forceinline__ u64 h2f2(unsigned h) {
    u64 r;
    asm("{\n\t.reg .b16 lo, hi;\n\t.reg .f32 flo, fhi;\n\t"
        "mov.b32 {lo, hi}, %1;\n\t"
        "cvt.f32.f16 flo, lo;\n\t"
        "cvt.f32.f16 fhi, hi;\n\t"
        "mov.b64 %0, {flo, fhi};\n\t}"
        : "=l"(r) : "r"(h));
    return r;
}
// fp16x2 fused multiply-add (HFMA2)
__device__ __forceinline__ unsigned hfma2(unsigned a, unsigned b, unsigned c) {
    unsigned d;
    asm("fma.rn.f16x2 %0, %1, %2, %3;" : "=r"(d) : "r"(a), "r"(b), "r"(c));
    return d;
}
// float -> replicated half2
__device__ __forceinline__ unsigned f2h2(float f) {
    unsigned r;
    asm("{\n\t.reg .b16 h;\n\tcvt.rn.f16.f32 h, %1;\n\t"
        "mov.b32 %0, {h, h};\n\t}" : "=r"(r) : "f"(f));
    return r;
}
// 16-B load, L2-only (no L1 allocation): keeps L1D free for the e-table.
__device__ __forceinline__ uint4 ldg_cg128(const uint4* p) {
    uint4 v;
    asm volatile("ld.global.cg.v4.u32 {%0, %1, %2, %3}, [%4];"
                 : "=r"(v.x), "=r"(v.y), "=r"(v.z), "=r"(v.w) : "l"(p));
    return v;
}

// ---------------------------------------------------------------------------
// Kernel 1: per-row precompute. One warp per row.
// ---------------------------------------------------------------------------
__global__ __launch_bounds__(256, 8)
void precompute_kernel(const float* __restrict__ x,
                       const float* __restrict__ att,
                       int N)
{
    const int row  = (blockIdx.x * blockDim.x + threadIdx.x) >> 5;
    const int lane = threadIdx.x & 31;
    if (row > N) return;

    float4 v = make_float4(0.f, 0.f, 0.f, 0.f);
    if (row < N) v = __ldg((const float4*)(x + (size_t)row * FD) + lane);
    const float4 a = __ldg((const float4*)(att + FD) + lane);

    // attention logit (full warp reduce)
    float dot = fmaf(v.x, a.x, fmaf(v.y, a.y, fmaf(v.z, a.z, v.w * a.w)));
#pragma unroll
    for (int off = 16; off; off >>= 1)
        dot += __shfl_xor_sync(0xffffffffu, dot, off);
    if (lane == 0) g_e[row] = dot;

    // capsule sum: capsule k = lane>>2 spans 4 lanes (16 elements), fp32 exact
    float cs = (v.x + v.y) + (v.z + v.w);
    cs += __shfl_xor_sync(0xffffffffu, cs, 1);
    cs += __shfl_xor_sync(0xffffffffu, cs, 2);

    // premultiplied fp16 row: z~ = x * s
    __half2 h0 = __float22half2_rn(make_float2(v.x * cs, v.y * cs));
    __half2 h1 = __float22half2_rn(make_float2(v.z * cs, v.w * cs));
    uint2 packed;
    packed.x = *reinterpret_cast<unsigned*>(&h0);
    packed.y = *reinterpret_cast<unsigned*>(&h1);
    ((uint2*)g_xh)[(size_t)row * 32 + lane] = packed;
}

// ---------------------------------------------------------------------------
// Kernel 2: main routing (R10 structure; gathers use .cg so the 200-KB e
// table stays resident in L1D). HALF-WARP per node; 16 lanes x one LDG.128
// per 256-B row; MLP=4 batches; HFMA2 accumulate, fp16 flush every 8.
// ---------------------------------------------------------------------------
__global__ __launch_bounds__(256, 6)
void routing_kernel(const float* __restrict__ x,
                    const int*   __restrict__ nbr,
                    float*       __restrict__ out,
                    int N)
{
    const int lane = threadIdx.x & 31;
    const int l    = lane & 15;            // lane within half-warp
    int n = blockIdx.x * 16 + (threadIdx.x >> 5) * 2 + (lane >> 4);
    if (n >= N) n = N - 1;                 // exact for N % 16 == 0

    // lane l holds neighbors m = 2l and 2l+1 (order irrelevant to the result)
    const int2  ii = __ldg((const int2*)(nbr + (size_t)n * NBRS) + l);
    const float e0 = __ldg(g_e + ii.x);    // L1-resident (gathers don't thrash)
    const float e1 = __ldg(g_e + ii.y);

    // softmax over the 32 neighbors, within the 16-lane group
    float mx = fmaxf(e0, e1);
#pragma unroll
    for (int off = 8; off; off >>= 1)
        mx = fmaxf(mx, __shfl_xor_sync(0xffffffffu, mx, off, 16));
    const float p0 = __expf(e0 - mx);
    const float p1 = __expf(e1 - mx);
    float sum = p0 + p1;
#pragma unroll
    for (int off = 8; off; off >>= 1)
        sum += __shfl_xor_sync(0xffffffffu, sum, off, 16);
    const float inv  = ACOEF / sum;
    const float wgt0 = p0 * inv;
    const float wgt1 = p1 * inv;

    u64 acc0 = 0, acc1 = 0, acc2 = 0, acc3 = 0;   // fp32 pairs (final)

#pragma unroll
    for (int ch = 0; ch < NBRS / 8; ++ch) {        // 8-neighbor fp16 chunks
        unsigned hac0 = 0, hac1 = 0, hac2 = 0, hac3 = 0;  // half2 partials
#pragma unroll
        for (int tb = 0; tb < 2; ++tb) {
            // ---- issue 4 independent gathers back-to-back (MLP = 4) ------
            uint4 zp[4];
#pragma unroll
            for (int j = 0; j < 4; ++j) {
                const int t  = ch * 8 + tb * 4 + j;    // compile-time const
                const int im = __shfl_sync(0xffffffffu,
                                           (t & 1) ? ii.y : ii.x, t >> 1, 16);
                zp[j] = ldg_cg128(&g_xh[(size_t)im * 16 + l]);   // L2-only
            }
            // ---- consume: HFMA2 with broadcast half2 weight ---------------
#pragma unroll
            for (int j = 0; j < 4; ++j) {
                const int      t  = ch * 8 + tb * 4 + j;
                const float    wf = __shfl_sync(0xffffffffu,
                                        (t & 1) ? wgt1 : wgt0, t >> 1, 16);
                const unsigned wh = f2h2(wf);
                hac0 = hfma2(zp[j].x, wh, hac0);
                hac1 = hfma2(zp[j].y, wh, hac1);
                hac2 = hfma2(zp[j].z, wh, hac2);
                hac3 = hfma2(zp[j].w, wh, hac3);
            }
        }
        // flush fp16 partials into fp32 accumulators
        acc0 = fadd2(acc0, h2f2(hac0));
        acc1 = fadd2(acc1, h2f2(hac1));
        acc2 = fadd2(acc2, h2f2(hac2));
        acc3 = fadd2(acc3, h2f2(hac3));
    }

    // unpack, add residual, store (lane l -> d = 8l..8l+7, fully coalesced)
    float a0,a1,a2,a3,a4,a5,a6,a7;
    upk2(acc0, a0, a1); upk2(acc1, a2, a3);
    upk2(acc2, a4, a5); upk2(acc3, a6, a7);

    const float4* xr = (const float4*)(x + (size_t)n * FD);
    const float4  x0 = __ldg(xr + 2 * l);
    const float4  x1 = __ldg(xr + 2 * l + 1);
    float4* orow = (float4*)(out + (size_t)n * FD);
    orow[2 * l]     = make_float4(a0 + x0.x, a1 + x0.y, a2 + x0.z, a3 + x0.w);
    orow[2 * l + 1] = make_float4(a4 + x1.x, a5 + x1.y, a6 + x1.z, a7 + x1.w);
}

extern "C" void kernel_launch(void* const* d_in, const int* in_sizes, int n_in,
                              void* d_out, int out_size)
{
    const float* x   = (const float*)d_in[0];   // (N, 128)
    const float* att = (const float*)d_in[1];   // (256, 1)
    const int*   nbr = (const int*)d_in[2];     // (N*32,)
    // d_in[3] = max_iter : provably unused (u never depends on routing var p)
    float* out = (float*)d_out;

    const int N = in_sizes[0] / FD;

    const int preBlocks  = (N + 1 + 7) / 8;     // rows 0..N (incl. pad record)
    precompute_kernel<<<preBlocks, 256>>>(x, att, N);

    const int mainBlocks = (N + 15) / 16;       // 16 nodes per 256-thread block
    routing_kernel<<<mainBlocks, 256>>>(x, nbr, out, N);
}